// round 1
// baseline (speedup 1.0000x reference)
#include <cuda_runtime.h>

#define S 512
#define C 16
#define ROW (S*C)

typedef unsigned long long u64;
typedef ulonglong2 u64x2;

static __device__ __forceinline__ u64 pack2f(float lo, float hi) {
    u64 r; asm("mov.b64 %0, {%1, %2};" : "=l"(r) : "f"(lo), "f"(hi)); return r;
}
static __device__ __forceinline__ u64 dup2f(float v) {
    u64 r; asm("mov.b64 %0, {%1, %1};" : "=l"(r) : "f"(v)); return r;
}
static __device__ __forceinline__ float2 unpk(u64 p) {
    float2 f; asm("mov.b64 {%0, %1}, %2;" : "=f"(f.x), "=f"(f.y) : "l"(p)); return f;
}
static __device__ __forceinline__ u64 ffma2(u64 a, u64 b, u64 c) {
    u64 d; asm("fma.rn.f32x2 %0, %1, %2, %3;" : "=l"(d) : "l"(a), "l"(b), "l"(c)); return d;
}
static __device__ __forceinline__ float swishf(float z) {
    return __fdividef(z, 1.0f + __expf(-z));
}
static __device__ __forceinline__ float getc(float4 v, int i) {
    switch (i & 3) { case 0: return v.x; case 1: return v.y; case 2: return v.z; default: return v.w; }
}

__global__ void __launch_bounds__(128) nca_step(
    const float* __restrict__ xin, const float* __restrict__ noise,
    const float* __restrict__ W1, const float* __restrict__ b1,
    const float* __restrict__ W2, const float* __restrict__ b2,
    const float* __restrict__ W3, const float* __restrict__ b3,
    float* __restrict__ out)
{
    __shared__ __align__(16) float sW1[80*64];
    __shared__ __align__(16) float sW2[64*32];
    __shared__ __align__(16) float sW3[32*16];
    __shared__ float sB1[64], sB2[32], sB3[16];

    for (int i = threadIdx.x; i < 80*64; i += 128) sW1[i] = W1[i];
    for (int i = threadIdx.x; i < 64*32; i += 128) sW2[i] = W2[i];
    for (int i = threadIdx.x; i < 32*16; i += 128) sW3[i] = W3[i];
    if (threadIdx.x < 64) sB1[threadIdx.x] = b1[threadIdx.x];
    else if (threadIdx.x < 96) sB2[threadIdx.x-64] = b2[threadIdx.x-64];
    else if (threadIdx.x < 112) sB3[threadIdx.x-96] = b3[threadIdx.x-96];
    __syncthreads();

    int tid = blockIdx.x * 128 + threadIdx.x;
    int pix = tid * 2;                       // even pixel; pair (pix, pix+1) same row
    int xx = pix & (S-1);
    int yy = (pix >> 9) & (S-1);
    bool tp = yy > 0, bt = yy < S-1, lf = xx > 0, rt = xx < S-2;

    const float* base = xin + (size_t)pix * C;

    // Layer-1 accumulators: packed output pairs, per pixel (A = pix, B = pix+1)
    u64 accA[32], accB[32];
    #pragma unroll
    for (int j = 0; j < 32; j++) {
        u64 bb = pack2f(sB1[2*j], sB1[2*j+1]);
        accA[j] = bb; accB[j] = bb;
    }

    #pragma unroll 1
    for (int cg = 0; cg < 4; cg++) {
        const float* p = base + cg*4;
        float4 z4 = make_float4(0.f,0.f,0.f,0.f);
        // 3 rows x 4 cols of float4 (4 channels), zero-padded at borders
        float4 t0 = (tp&&lf) ? *(const float4*)(p - ROW - C)   : z4;
        float4 t1 = tp       ? *(const float4*)(p - ROW)       : z4;
        float4 t2 = tp       ? *(const float4*)(p - ROW + C)   : z4;
        float4 t3 = (tp&&rt) ? *(const float4*)(p - ROW + 2*C) : z4;
        float4 m0 = lf       ? *(const float4*)(p - C)         : z4;
        float4 m1 =            *(const float4*)(p);
        float4 m2 =            *(const float4*)(p + C);
        float4 m3 = rt       ? *(const float4*)(p + 2*C)       : z4;
        float4 q0 = (bt&&lf) ? *(const float4*)(p + ROW - C)   : z4;
        float4 q1 = bt       ? *(const float4*)(p + ROW)       : z4;
        float4 q2 = bt       ? *(const float4*)(p + ROW + C)   : z4;
        float4 q3 = (bt&&rt) ? *(const float4*)(p + ROW + 2*C) : z4;

        #pragma unroll
        for (int cc = 0; cc < 4; cc++) {
            float a00=getc(t0,cc), a01=getc(t1,cc), a02=getc(t2,cc), a03=getc(t3,cc);
            float a10=getc(m0,cc), a11=getc(m1,cc), a12=getc(m2,cc), a13=getc(m3,cc);
            float a20=getc(q0,cc), a21=getc(q1,cc), a22=getc(q2,cc), a23=getc(q3,cc);

            // perceive features: identity, sobel_x, sobel_y, laplacian, average
            float fA[5], fB[5];
            {
                float e  = a01+a10+a12+a21;
                float co = a00+a02+a20+a22;
                fA[0] = a11;
                fA[1] = ((a02-a00) + 2.f*(a12-a10) + (a22-a20)) * 0.125f;
                fA[2] = ((a20-a00) + 2.f*(a21-a01) + (a22-a02)) * 0.125f;
                fA[3] = 0.25f*co + 0.5f*e - 3.f*a11;
                fA[4] = (co + e + a11) * (1.f/9.f);
            }
            {
                float e  = a02+a11+a13+a22;
                float co = a01+a03+a21+a23;
                fB[0] = a12;
                fB[1] = ((a03-a01) + 2.f*(a13-a11) + (a23-a21)) * 0.125f;
                fB[2] = ((a21-a01) + 2.f*(a22-a02) + (a23-a03)) * 0.125f;
                fB[3] = 0.25f*co + 0.5f*e - 3.f*a12;
                fB[4] = (co + e + a12) * (1.f/9.f);
            }
            #pragma unroll
            for (int f = 0; f < 5; f++) {
                u64 dA = dup2f(fA[f]);
                u64 dB = dup2f(fB[f]);
                const u64x2* w = (const u64x2*)&sW1[((cg*4+cc)*5 + f) * 64];
                #pragma unroll
                for (int j = 0; j < 16; j++) {
                    u64x2 wv = w[j];
                    accA[2*j]   = ffma2(dA, wv.x, accA[2*j]);
                    accA[2*j+1] = ffma2(dA, wv.y, accA[2*j+1]);
                    accB[2*j]   = ffma2(dB, wv.x, accB[2*j]);
                    accB[2*j+1] = ffma2(dB, wv.y, accB[2*j+1]);
                }
            }
        }
    }

    // swish in place -> a1 stays packed in accA/accB
    #pragma unroll
    for (int j = 0; j < 32; j++) {
        float2 a = unpk(accA[j]); accA[j] = pack2f(swishf(a.x), swishf(a.y));
        float2 b = unpk(accB[j]); accB[j] = pack2f(swishf(b.x), swishf(b.y));
    }

    // layer 2: 64 -> 32
    u64 c2A[16], c2B[16];
    #pragma unroll
    for (int j = 0; j < 16; j++) {
        u64 bb = pack2f(sB2[2*j], sB2[2*j+1]);
        c2A[j] = bb; c2B[j] = bb;
    }
    #pragma unroll
    for (int k = 0; k < 64; k++) {
        float2 aa = unpk(accA[k>>1]);
        float2 ab = unpk(accB[k>>1]);
        float sa = (k & 1) ? aa.y : aa.x;
        float sb = (k & 1) ? ab.y : ab.x;
        u64 dA = dup2f(sa), dB = dup2f(sb);
        const u64x2* w = (const u64x2*)&sW2[k * 32];
        #pragma unroll
        for (int j = 0; j < 8; j++) {
            u64x2 wv = w[j];
            c2A[2*j]   = ffma2(dA, wv.x, c2A[2*j]);
            c2A[2*j+1] = ffma2(dA, wv.y, c2A[2*j+1]);
            c2B[2*j]   = ffma2(dB, wv.x, c2B[2*j]);
            c2B[2*j+1] = ffma2(dB, wv.y, c2B[2*j+1]);
        }
    }
    #pragma unroll
    for (int j = 0; j < 16; j++) {
        float2 a = unpk(c2A[j]); c2A[j] = pack2f(swishf(a.x), swishf(a.y));
        float2 b = unpk(c2B[j]); c2B[j] = pack2f(swishf(b.x), swishf(b.y));
    }

    // layer 3: 32 -> 16 (linear)
    u64 c3A[8], c3B[8];
    #pragma unroll
    for (int j = 0; j < 8; j++) {
        u64 bb = pack2f(sB3[2*j], sB3[2*j+1]);
        c3A[j] = bb; c3B[j] = bb;
    }
    #pragma unroll
    for (int k = 0; k < 32; k++) {
        float2 aa = unpk(c2A[k>>1]);
        float2 ab = unpk(c2B[k>>1]);
        float sa = (k & 1) ? aa.y : aa.x;
        float sb = (k & 1) ? ab.y : ab.x;
        u64 dA = dup2f(sa), dB = dup2f(sb);
        const u64x2* w = (const u64x2*)&sW3[k * 16];
        #pragma unroll
        for (int j = 0; j < 4; j++) {
            u64x2 wv = w[j];
            c3A[2*j]   = ffma2(dA, wv.x, c3A[2*j]);
            c3A[2*j+1] = ffma2(dA, wv.y, c3A[2*j+1]);
            c3B[2*j]   = ffma2(dB, wv.x, c3B[2*j]);
            c3B[2*j+1] = ffma2(dB, wv.y, c3B[2*j+1]);
        }
    }

    // epilogue: out = x + dx * (noise <= 0.5)
    float mA = (noise[pix]   <= 0.5f) ? 1.f : 0.f;
    float mB = (noise[pix+1] <= 0.5f) ? 1.f : 0.f;
    float* o = out + (size_t)pix * C;
    #pragma unroll
    for (int g = 0; g < 4; g++) {
        float4 xv = *(const float4*)(base + g*4);
        float2 d0 = unpk(c3A[2*g]);
        float2 d1 = unpk(c3A[2*g+1]);
        float4 ov = make_float4(xv.x + d0.x*mA, xv.y + d0.y*mA,
                                xv.z + d1.x*mA, xv.w + d1.y*mA);
        *(float4*)(o + g*4) = ov;
    }
    #pragma unroll
    for (int g = 0; g < 4; g++) {
        float4 xv = *(const float4*)(base + C + g*4);
        float2 d0 = unpk(c3B[2*g]);
        float2 d1 = unpk(c3B[2*g+1]);
        float4 ov = make_float4(xv.x + d0.x*mB, xv.y + d0.y*mB,
                                xv.z + d1.x*mB, xv.w + d1.y*mB);
        *(float4*)(o + C + g*4) = ov;
    }
}

extern "C" void kernel_launch(void* const* d_in, const int* in_sizes, int n_in,
                              void* d_out, int out_size) {
    const float* x     = (const float*)d_in[0];
    const float* noise = (const float*)d_in[1];
    const float* W1    = (const float*)d_in[2];
    const float* b1    = (const float*)d_in[3];
    const float* W2    = (const float*)d_in[4];
    const float* b2    = (const float*)d_in[5];
    const float* W3    = (const float*)d_in[6];
    const float* b3    = (const float*)d_in[7];

    int total_pixels = in_sizes[1];          // B*S*S from noise element count
    int nthreads = total_pixels / 2;         // 2 pixels per thread
    int block = 128;
    int grid = (nthreads + block - 1) / block;
    nca_step<<<grid, block>>>(x, noise, W1, b1, W2, b2, W3, b3, (float*)d_out);
}

// round 2
// speedup vs baseline: 1.1914x; 1.1914x over previous
#include <cuda_runtime.h>

#define S 512
#define C 16
#define TILE_COLS 130
#define PSTRIDE 20                 // padded floats per pixel in smem tile (bank-conflict-free)
#define TILE_FLOATS (4*TILE_COLS*PSTRIDE)   // 10400
#define OFF_W1 TILE_FLOATS
#define OFF_W2 (OFF_W1 + 80*64)
#define OFF_W3 (OFF_W2 + 64*32)
#define OFF_B1 (OFF_W3 + 32*16)
#define OFF_B2 (OFF_B1 + 64)
#define OFF_B3 (OFF_B2 + 32)
#define SMEM_FLOATS (OFF_B3 + 16)
#define SMEM_BYTES (SMEM_FLOATS * 4)

typedef unsigned long long u64;
typedef ulonglong2 u64x2;

static __device__ __forceinline__ u64 pack2f(float lo, float hi) {
    u64 r; asm("mov.b64 %0, {%1, %2};" : "=l"(r) : "f"(lo), "f"(hi)); return r;
}
static __device__ __forceinline__ u64 dup2f(float v) {
    u64 r; asm("mov.b64 %0, {%1, %1};" : "=l"(r) : "f"(v)); return r;
}
static __device__ __forceinline__ float2 unpk(u64 p) {
    float2 f; asm("mov.b64 {%0, %1}, %2;" : "=f"(f.x), "=f"(f.y) : "l"(p)); return f;
}
static __device__ __forceinline__ u64 ffma2(u64 a, u64 b, u64 c) {
    u64 d; asm("fma.rn.f32x2 %0, %1, %2, %3;" : "=l"(d) : "l"(a), "l"(b), "l"(c)); return d;
}
static __device__ __forceinline__ float swishf(float z) {
    return __fdividef(z, 1.0f + __expf(-z));
}
static __device__ __forceinline__ float getc(float4 v, int i) {
    switch (i & 3) { case 0: return v.x; case 1: return v.y; case 2: return v.z; default: return v.w; }
}

__global__ void __launch_bounds__(128) nca_step(
    const float* __restrict__ xin, const float* __restrict__ noise,
    const float* __restrict__ W1, const float* __restrict__ b1,
    const float* __restrict__ W2, const float* __restrict__ b2,
    const float* __restrict__ W3, const float* __restrict__ b3,
    float* __restrict__ out)
{
    extern __shared__ __align__(16) float smem[];
    float* tile = smem;
    float* sW1 = smem + OFF_W1;
    float* sW2 = smem + OFF_W2;
    float* sW3 = smem + OFF_W3;
    float* sB1 = smem + OFF_B1;
    float* sB2 = smem + OFF_B2;
    float* sB3 = smem + OFF_B3;

    const int tid = threadIdx.x;

    // ---- stage weights + biases ----
    for (int i = tid; i < 80*64; i += 128) sW1[i] = W1[i];
    for (int i = tid; i < 64*32; i += 128) sW2[i] = W2[i];
    for (int i = tid; i < 32*16; i += 128) sW3[i] = W3[i];
    if (tid < 64) sB1[tid] = b1[tid];
    else if (tid < 96) sB2[tid-64] = b2[tid-64];
    else if (tid < 112) sB3[tid-96] = b3[tid-96];

    // ---- block -> (batch, row pair y0/y0+1, column block c0) ----
    const int blk  = blockIdx.x;
    const int c0   = (blk & 3) * 128;
    const int rp   = blk >> 2;
    const int b    = rp >> 8;
    const int y0   = (rp & 255) * 2;

    // ---- coalesced load of input tile: rows y0-1..y0+2, cols c0-1..c0+128, zero halo ----
    const float4* xin4 = (const float4*)xin;
    #pragma unroll
    for (int it = 0; it < 4*520/128 + 1; it++) {
        int i = tid + it * 128;
        if (i < 4*520) {
            int r   = i / 520;
            int rem = i - r * 520;
            int pc  = rem >> 2;          // tile pixel col 0..129
            int ch4 = rem & 3;           // which float4 of the 16 channels
            int gy  = y0 - 1 + r;
            int gx  = c0 - 1 + pc;
            float4 v = make_float4(0.f, 0.f, 0.f, 0.f);
            if ((unsigned)gy < S && (unsigned)gx < S)
                v = xin4[(((size_t)b * S + gy) * S + gx) * 4 + ch4];
            *(float4*)(tile + (r * TILE_COLS + pc) * PSTRIDE + ch4 * 4) = v;
        }
    }
    __syncthreads();

    const int tc = tid + 1;              // tile col of this lane's pixel column

    // ---- layer-1 accumulators: pixel A = (y0, x), pixel B = (y0+1, x) ----
    u64 accA[32], accB[32];
    #pragma unroll
    for (int j = 0; j < 32; j++) {
        u64 bb = pack2f(sB1[2*j], sB1[2*j+1]);
        accA[j] = bb; accB[j] = bb;
    }

    #pragma unroll 1
    for (int cg = 0; cg < 4; cg++) {
        float4 t[4][3];
        #pragma unroll
        for (int r = 0; r < 4; r++)
            #pragma unroll
            for (int c = 0; c < 3; c++)
                t[r][c] = *(const float4*)(tile + (r * TILE_COLS + tc - 1 + c) * PSTRIDE + cg * 4);

        float fA[4][5], fB[4][5];
        #pragma unroll
        for (int cc = 0; cc < 4; cc++) {
            float a[4][3];
            #pragma unroll
            for (int r = 0; r < 4; r++)
                #pragma unroll
                for (int c = 0; c < 3; c++)
                    a[r][c] = getc(t[r][c], cc);

            {   // pixel A: rows 0..2
                float e  = a[0][1] + a[1][0] + a[1][2] + a[2][1];
                float co = a[0][0] + a[0][2] + a[2][0] + a[2][2];
                fA[cc][0] = a[1][1];
                fA[cc][1] = ((a[0][2]-a[0][0]) + 2.f*(a[1][2]-a[1][0]) + (a[2][2]-a[2][0])) * 0.125f;
                fA[cc][2] = ((a[2][0]-a[0][0]) + 2.f*(a[2][1]-a[0][1]) + (a[2][2]-a[0][2])) * 0.125f;
                fA[cc][3] = 0.25f*co + 0.5f*e - 3.f*a[1][1];
                fA[cc][4] = (co + e + a[1][1]) * (1.f/9.f);
            }
            {   // pixel B: rows 1..3
                float e  = a[1][1] + a[2][0] + a[2][2] + a[3][1];
                float co = a[1][0] + a[1][2] + a[3][0] + a[3][2];
                fB[cc][0] = a[2][1];
                fB[cc][1] = ((a[1][2]-a[1][0]) + 2.f*(a[2][2]-a[2][0]) + (a[3][2]-a[3][0])) * 0.125f;
                fB[cc][2] = ((a[3][0]-a[1][0]) + 2.f*(a[3][1]-a[1][1]) + (a[3][2]-a[1][2])) * 0.125f;
                fB[cc][3] = 0.25f*co + 0.5f*e - 3.f*a[2][1];
                fB[cc][4] = (co + e + a[2][1]) * (1.f/9.f);
            }
        }

        #pragma unroll
        for (int cc = 0; cc < 4; cc++) {
            #pragma unroll
            for (int f = 0; f < 5; f++) {
                u64 dA = dup2f(fA[cc][f]);
                u64 dB = dup2f(fB[cc][f]);
                const u64x2* w = (const u64x2*)&sW1[((cg*4 + cc)*5 + f) * 64];
                #pragma unroll
                for (int j = 0; j < 16; j++) {
                    u64x2 wv = w[j];
                    accA[2*j]   = ffma2(dA, wv.x, accA[2*j]);
                    accA[2*j+1] = ffma2(dA, wv.y, accA[2*j+1]);
                    accB[2*j]   = ffma2(dB, wv.x, accB[2*j]);
                    accB[2*j+1] = ffma2(dB, wv.y, accB[2*j+1]);
                }
            }
        }
    }

    // swish in place
    #pragma unroll
    for (int j = 0; j < 32; j++) {
        float2 a = unpk(accA[j]); accA[j] = pack2f(swishf(a.x), swishf(a.y));
        float2 bv = unpk(accB[j]); accB[j] = pack2f(swishf(bv.x), swishf(bv.y));
    }

    // ---- layer 2: 64 -> 32 ----
    u64 c2A[16], c2B[16];
    #pragma unroll
    for (int j = 0; j < 16; j++) {
        u64 bb = pack2f(sB2[2*j], sB2[2*j+1]);
        c2A[j] = bb; c2B[j] = bb;
    }
    #pragma unroll
    for (int k = 0; k < 64; k++) {
        float2 aa = unpk(accA[k>>1]);
        float2 ab = unpk(accB[k>>1]);
        float sa = (k & 1) ? aa.y : aa.x;
        float sb = (k & 1) ? ab.y : ab.x;
        u64 dA = dup2f(sa), dB = dup2f(sb);
        const u64x2* w = (const u64x2*)&sW2[k * 32];
        #pragma unroll
        for (int j = 0; j < 8; j++) {
            u64x2 wv = w[j];
            c2A[2*j]   = ffma2(dA, wv.x, c2A[2*j]);
            c2A[2*j+1] = ffma2(dA, wv.y, c2A[2*j+1]);
            c2B[2*j]   = ffma2(dB, wv.x, c2B[2*j]);
            c2B[2*j+1] = ffma2(dB, wv.y, c2B[2*j+1]);
        }
    }
    #pragma unroll
    for (int j = 0; j < 16; j++) {
        float2 a = unpk(c2A[j]); c2A[j] = pack2f(swishf(a.x), swishf(a.y));
        float2 bv = unpk(c2B[j]); c2B[j] = pack2f(swishf(bv.x), swishf(bv.y));
    }

    // ---- layer 3: 32 -> 16 (linear) ----
    u64 c3A[8], c3B[8];
    #pragma unroll
    for (int j = 0; j < 8; j++) {
        u64 bb = pack2f(sB3[2*j], sB3[2*j+1]);
        c3A[j] = bb; c3B[j] = bb;
    }
    #pragma unroll
    for (int k = 0; k < 32; k++) {
        float2 aa = unpk(c2A[k>>1]);
        float2 ab = unpk(c2B[k>>1]);
        float sa = (k & 1) ? aa.y : aa.x;
        float sb = (k & 1) ? ab.y : ab.x;
        u64 dA = dup2f(sa), dB = dup2f(sb);
        const u64x2* w = (const u64x2*)&sW3[k * 16];
        #pragma unroll
        for (int j = 0; j < 4; j++) {
            u64x2 wv = w[j];
            c3A[2*j]   = ffma2(dA, wv.x, c3A[2*j]);
            c3A[2*j+1] = ffma2(dA, wv.y, c3A[2*j+1]);
            c3B[2*j]   = ffma2(dB, wv.x, c3B[2*j]);
            c3B[2*j+1] = ffma2(dB, wv.y, c3B[2*j+1]);
        }
    }

    // ---- epilogue: out = x + dx * (noise <= 0.5) ----
    const size_t pA = ((size_t)b * S + y0) * S + c0 + tid;
    const size_t pB = pA + S;
    float mA = (noise[pA] <= 0.5f) ? 1.f : 0.f;
    float mB = (noise[pB] <= 0.5f) ? 1.f : 0.f;

    float* oA = out + pA * C;
    float* oB = out + pB * C;
    const float* xA = tile + (1 * TILE_COLS + tc) * PSTRIDE;
    const float* xB = tile + (2 * TILE_COLS + tc) * PSTRIDE;
    #pragma unroll
    for (int g = 0; g < 4; g++) {
        float4 xv = *(const float4*)(xA + g*4);
        float2 d0 = unpk(c3A[2*g]);
        float2 d1 = unpk(c3A[2*g+1]);
        *(float4*)(oA + g*4) = make_float4(xv.x + d0.x*mA, xv.y + d0.y*mA,
                                           xv.z + d1.x*mA, xv.w + d1.y*mA);
    }
    #pragma unroll
    for (int g = 0; g < 4; g++) {
        float4 xv = *(const float4*)(xB + g*4);
        float2 d0 = unpk(c3B[2*g]);
        float2 d1 = unpk(c3B[2*g+1]);
        *(float4*)(oB + g*4) = make_float4(xv.x + d0.x*mB, xv.y + d0.y*mB,
                                           xv.z + d1.x*mB, xv.w + d1.y*mB);
    }
}

extern "C" void kernel_launch(void* const* d_in, const int* in_sizes, int n_in,
                              void* d_out, int out_size) {
    const float* x     = (const float*)d_in[0];
    const float* noise = (const float*)d_in[1];
    const float* W1    = (const float*)d_in[2];
    const float* b1    = (const float*)d_in[3];
    const float* W2    = (const float*)d_in[4];
    const float* b2    = (const float*)d_in[5];
    const float* W3    = (const float*)d_in[6];
    const float* b3    = (const float*)d_in[7];

    // Idempotent; persists on the function after the first (uncaptured) correctness call.
    cudaFuncSetAttribute(nca_step, cudaFuncAttributeMaxDynamicSharedMemorySize, SMEM_BYTES);

    // grid: 4 batches * 256 row-pairs * 4 column blocks = 4096 blocks of 128 threads,
    // each block covers 2 rows x 128 cols = 256 pixels.
    nca_step<<<4096, 128, SMEM_BYTES>>>(x, noise, W1, b1, W2, b2, W3, b3, (float*)d_out);
}

// round 4
// speedup vs baseline: 1.5238x; 1.2790x over previous
#include <cuda_runtime.h>
#include <cstdint>

#define S 512
#define C 16
#define TILE_COLS 130
#define PSTRIDE 20
#define PP 136                 // pixel-dim stride (in 4-byte units) for transposed activations

// ---- smem byte offsets ----
#define OFF_YHI   0
#define OFF_YLO   (40*PP*4)                       // 21760
#define OFF_WREG  (2*40*PP*4)                     // 43520 (tile aliases this region)
#define OFF_TILE  OFF_WREG
#define W1P 44
#define W2P 36
#define W3P 20
#define OFF_W1H OFF_WREG
#define OFF_W1L (OFF_W1H + 64*W1P*4)              // +11264
#define OFF_W2H (OFF_W1L + 64*W1P*4)
#define OFF_W2L (OFF_W2H + 32*W2P*4)              // +4608
#define OFF_W3H (OFF_W2L + 32*W2P*4)
#define OFF_W3L (OFF_W3H + 16*W3P*4)              // +1280
#define OFF_B1  (OFF_W3L + 16*W3P*4)
#define OFF_B2  (OFF_B1 + 64*4)
#define OFF_B3  (OFF_B2 + 32*4)
#define SMEM_BYTES (OFF_B3 + 16*4)                // 78272

__device__ uint32_t gW1h[64*W1P], gW1l[64*W1P];
__device__ uint32_t gW2h[32*W2P], gW2l[32*W2P];
__device__ uint32_t gW3h[16*W3P], gW3l[16*W3P];

// ---------------- helpers ----------------
static __device__ __forceinline__ uint32_t pkbf(float hi, float lo) {
    uint32_t d; asm("cvt.rn.bf16x2.f32 %0, %1, %2;" : "=r"(d) : "f"(hi), "f"(lo)); return d;
}
static __device__ __forceinline__ float bf_lo(uint32_t v) { return __uint_as_float(v << 16); }
static __device__ __forceinline__ float bf_hi(uint32_t v) { return __uint_as_float(v & 0xffff0000u); }
static __device__ __forceinline__ float swishf(float z) {
    return __fdividef(z, 1.0f + __expf(-z));
}
static __device__ __forceinline__ float getc(float4 v, int i) {
    switch (i & 3) { case 0: return v.x; case 1: return v.y; case 2: return v.z; default: return v.w; }
}
static __device__ __forceinline__ void mma_bf16(float* c, const uint32_t* a,
                                                uint32_t b0, uint32_t b1) {
    asm("mma.sync.aligned.m16n8k16.row.col.f32.bf16.bf16.f32 "
        "{%0,%1,%2,%3}, {%4,%5,%6,%7}, {%8,%9}, {%0,%1,%2,%3};"
        : "+f"(c[0]), "+f"(c[1]), "+f"(c[2]), "+f"(c[3])
        : "r"(a[0]), "r"(a[1]), "r"(a[2]), "r"(a[3]), "r"(b0), "r"(b1));
}

// ---------------- weight prep: transpose + bf16 hi/lo split + pad ----------------
__global__ void prep_weights(const float* __restrict__ W1, const float* __restrict__ W2,
                             const float* __restrict__ W3) {
    int i0 = blockIdx.x * blockDim.x + threadIdx.x;
    int nt = gridDim.x * blockDim.x;
    for (int i = i0; i < 64 * W1P; i += nt) {
        int n = i / W1P, jp = i % W1P;
        int k0 = 2 * jp, k1 = k0 + 1;
        float w0 = (k0 < 80) ? W1[k0 * 64 + n] : 0.f;
        float w1v = (k1 < 80) ? W1[k1 * 64 + n] : 0.f;
        uint32_t h = pkbf(w1v, w0);
        gW1h[i] = h;
        gW1l[i] = pkbf(w1v - bf_hi(h), w0 - bf_lo(h));
    }
    for (int i = i0; i < 32 * W2P; i += nt) {
        int n = i / W2P, jp = i % W2P;
        int k0 = 2 * jp, k1 = k0 + 1;
        float w0 = (k0 < 64) ? W2[k0 * 32 + n] : 0.f;
        float w1v = (k1 < 64) ? W2[k1 * 32 + n] : 0.f;
        uint32_t h = pkbf(w1v, w0);
        gW2h[i] = h;
        gW2l[i] = pkbf(w1v - bf_hi(h), w0 - bf_lo(h));
    }
    for (int i = i0; i < 16 * W3P; i += nt) {
        int n = i / W3P, jp = i % W3P;
        int k0 = 2 * jp, k1 = k0 + 1;
        float w0 = (k0 < 32) ? W3[k0 * 16 + n] : 0.f;
        float w1v = (k1 < 32) ? W3[k1 * 16 + n] : 0.f;
        uint32_t h = pkbf(w1v, w0);
        gW3h[i] = h;
        gW3l[i] = pkbf(w1v - bf_hi(h), w0 - bf_lo(h));
    }
}

// ---------------- main kernel ----------------
__global__ void __launch_bounds__(128) nca_mma(
    const float* __restrict__ xin, const float* __restrict__ noise,
    const float* __restrict__ b1, const float* __restrict__ b2, const float* __restrict__ b3,
    float* __restrict__ out)
{
    extern __shared__ __align__(16) char smem[];
    float* tile = (float*)(smem + OFF_TILE);
    uint32_t* sYh = (uint32_t*)(smem + OFF_YHI);
    uint32_t* sYl = (uint32_t*)(smem + OFF_YLO);

    const int tid = threadIdx.x;
    const int lane = tid & 31;
    const int R = (tid >> 5) * 32;
    const int g = lane >> 2;
    const int t = lane & 3;

    // block -> (batch, row, column block)
    const int blk = blockIdx.x;
    const int c0 = (blk & 3) * 128;
    const int y  = (blk >> 2) & (S - 1);
    const int b  = blk >> 11;

    // ---- tile load: rows y-1..y+1, cols c0-1..c0+128, zero halo ----
    const float4* xin4 = (const float4*)xin;
    #pragma unroll
    for (int it = 0; it < 13; it++) {
        int i = tid + it * 128;
        if (i < 3 * 520) {
            int r = i / 520, rem = i - r * 520;
            int pc = rem >> 2, ch4 = rem & 3;
            int gy = y - 1 + r, gx = c0 - 1 + pc;
            float4 v = make_float4(0.f, 0.f, 0.f, 0.f);
            if ((unsigned)gy < S && (unsigned)gx < S)
                v = xin4[(((size_t)b * S + gy) * S + gx) * 4 + ch4];
            *(float4*)(tile + (r * TILE_COLS + pc) * PSTRIDE + ch4 * 4) = v;
        }
    }
    __syncthreads();

    // ---- perceive: 80 features, pack bf16 hi/lo pairs, store transposed ----
    const int tc = tid + 1;
    #pragma unroll
    for (int cg = 0; cg < 4; cg++) {
        float4 tt[3][3];
        #pragma unroll
        for (int r = 0; r < 3; r++)
            #pragma unroll
            for (int c = 0; c < 3; c++)
                tt[r][c] = *(const float4*)(tile + (r * TILE_COLS + tc - 1 + c) * PSTRIDE + cg * 4);
        float f[20];
        #pragma unroll
        for (int cc = 0; cc < 4; cc++) {
            float a[3][3];
            #pragma unroll
            for (int r = 0; r < 3; r++)
                #pragma unroll
                for (int c = 0; c < 3; c++)
                    a[r][c] = getc(tt[r][c], cc);
            float e  = a[0][1] + a[1][0] + a[1][2] + a[2][1];
            float co = a[0][0] + a[0][2] + a[2][0] + a[2][2];
            int bs = cc * 5;
            f[bs + 0] = a[1][1];
            f[bs + 1] = ((a[0][2]-a[0][0]) + 2.f*(a[1][2]-a[1][0]) + (a[2][2]-a[2][0])) * 0.125f;
            f[bs + 2] = ((a[2][0]-a[0][0]) + 2.f*(a[2][1]-a[0][1]) + (a[2][2]-a[0][2])) * 0.125f;
            f[bs + 3] = 0.25f*co + 0.5f*e - 3.f*a[1][1];
            f[bs + 4] = (co + e + a[1][1]) * (1.f/9.f);
        }
        #pragma unroll
        for (int i = 0; i < 10; i++) {
            uint32_t h = pkbf(f[2*i+1], f[2*i]);
            uint32_t l = pkbf(f[2*i+1] - bf_hi(h), f[2*i] - bf_lo(h));
            int ro = (cg * 10 + i) * PP + tid;
            sYh[ro] = h;
            sYl[ro] = l;
        }
    }
    __syncthreads();   // tile reads done everywhere; now overwrite tile with weights

    // ---- stage weights + biases (aliases tile region) ----
    {
        uint4* d;
        const uint4* s;
        d = (uint4*)(smem + OFF_W1H); s = (const uint4*)gW1h;
        for (int i = tid; i < 64*W1P/4; i += 128) d[i] = s[i];
        d = (uint4*)(smem + OFF_W1L); s = (const uint4*)gW1l;
        for (int i = tid; i < 64*W1P/4; i += 128) d[i] = s[i];
        d = (uint4*)(smem + OFF_W2H); s = (const uint4*)gW2h;
        for (int i = tid; i < 32*W2P/4; i += 128) d[i] = s[i];
        d = (uint4*)(smem + OFF_W2L); s = (const uint4*)gW2l;
        for (int i = tid; i < 32*W2P/4; i += 128) d[i] = s[i];
        d = (uint4*)(smem + OFF_W3H); s = (const uint4*)gW3h;
        for (int i = tid; i < 16*W3P/4; i += 128) d[i] = s[i];
        d = (uint4*)(smem + OFF_W3L); s = (const uint4*)gW3l;
        for (int i = tid; i < 16*W3P/4; i += 128) d[i] = s[i];
        float* B1 = (float*)(smem + OFF_B1);
        float* B2 = (float*)(smem + OFF_B2);
        float* B3 = (float*)(smem + OFF_B3);
        if (tid < 64) B1[tid] = b1[tid];
        else if (tid < 96) B2[tid-64] = b2[tid-64];
        else if (tid < 112) B3[tid-96] = b3[tid-96];
    }
    __syncthreads();

    const uint32_t* w1h = (const uint32_t*)(smem + OFF_W1H);
    const uint32_t* w1l = (const uint32_t*)(smem + OFF_W1L);
    const uint32_t* w2h = (const uint32_t*)(smem + OFF_W2H);
    const uint32_t* w2l = (const uint32_t*)(smem + OFF_W2L);
    const uint32_t* w3h = (const uint32_t*)(smem + OFF_W3H);
    const uint32_t* w3l = (const uint32_t*)(smem + OFF_W3L);
    const float2* B1v = (const float2*)(smem + OFF_B1);
    const float2* B2v = (const float2*)(smem + OFF_B2);
    const float2* B3v = (const float2*)(smem + OFF_B3);

    const int c00 = R + g, c01 = R + g + 8, c10 = R + 16 + g, c11 = R + 24 + g;

    // ================= layer 1: [128x80] x [80x64] =================
    float acc1[8][2][4];
    #pragma unroll
    for (int n = 0; n < 8; n++)
        #pragma unroll
        for (int m = 0; m < 2; m++)
            #pragma unroll
            for (int r = 0; r < 4; r++) acc1[n][m][r] = 0.f;

    #pragma unroll
    for (int kc = 0; kc < 5; kc++) {
        int r0 = kc * 8 + t, r1 = r0 + 4;
        uint32_t ah[2][4], al[2][4];
        ah[0][0] = sYh[r0*PP + c00]; ah[0][1] = sYh[r0*PP + c01];
        ah[0][2] = sYh[r1*PP + c00]; ah[0][3] = sYh[r1*PP + c01];
        ah[1][0] = sYh[r0*PP + c10]; ah[1][1] = sYh[r0*PP + c11];
        ah[1][2] = sYh[r1*PP + c10]; ah[1][3] = sYh[r1*PP + c11];
        al[0][0] = sYl[r0*PP + c00]; al[0][1] = sYl[r0*PP + c01];
        al[0][2] = sYl[r1*PP + c00]; al[0][3] = sYl[r1*PP + c01];
        al[1][0] = sYl[r0*PP + c10]; al[1][1] = sYl[r0*PP + c11];
        al[1][2] = sYl[r1*PP + c10]; al[1][3] = sYl[r1*PP + c11];
        #pragma unroll
        for (int n = 0; n < 8; n++) {
            int wr = (n*8 + g) * W1P;
            uint32_t bh0 = w1h[wr + r0], bh1 = w1h[wr + r1];
            uint32_t bl0 = w1l[wr + r0], bl1 = w1l[wr + r1];
            #pragma unroll
            for (int m = 0; m < 2; m++) {
                mma_bf16(acc1[n][m], ah[m], bh0, bh1);
                mma_bf16(acc1[n][m], ah[m], bl0, bl1);
                mma_bf16(acc1[n][m], al[m], bh0, bh1);
            }
        }
    }

    // swish + bias -> H1 (pair-rows 0..31), hi/lo
    #pragma unroll
    for (int n = 0; n < 8; n++) {
        float2 bb = B1v[n*4 + t];
        #pragma unroll
        for (int m = 0; m < 2; m++) {
            int rA = R + m*16 + g, rB = rA + 8;
            float s0 = swishf(acc1[n][m][0] + bb.x);
            float s1 = swishf(acc1[n][m][1] + bb.y);
            float s2 = swishf(acc1[n][m][2] + bb.x);
            float s3 = swishf(acc1[n][m][3] + bb.y);
            uint32_t h01 = pkbf(s1, s0);
            uint32_t l01 = pkbf(s1 - bf_hi(h01), s0 - bf_lo(h01));
            uint32_t h23 = pkbf(s3, s2);
            uint32_t l23 = pkbf(s3 - bf_hi(h23), s2 - bf_lo(h23));
            int ro = (n*4 + t) * PP;
            sYh[ro + rA] = h01; sYl[ro + rA] = l01;
            sYh[ro + rB] = h23; sYl[ro + rB] = l23;
        }
    }
    __syncwarp();

    // ================= layer 2: [128x64] x [64x32] =================
    float acc2[4][2][4];
    #pragma unroll
    for (int n = 0; n < 4; n++)
        #pragma unroll
        for (int m = 0; m < 2; m++)
            #pragma unroll
            for (int r = 0; r < 4; r++) acc2[n][m][r] = 0.f;

    #pragma unroll
    for (int kc = 0; kc < 4; kc++) {
        int r0 = kc * 8 + t, r1 = r0 + 4;
        uint32_t ah[2][4], al[2][4];
        ah[0][0] = sYh[r0*PP + c00]; ah[0][1] = sYh[r0*PP + c01];
        ah[0][2] = sYh[r1*PP + c00]; ah[0][3] = sYh[r1*PP + c01];
        ah[1][0] = sYh[r0*PP + c10]; ah[1][1] = sYh[r0*PP + c11];
        ah[1][2] = sYh[r1*PP + c10]; ah[1][3] = sYh[r1*PP + c11];
        al[0][0] = sYl[r0*PP + c00]; al[0][1] = sYl[r0*PP + c01];
        al[0][2] = sYl[r1*PP + c00]; al[0][3] = sYl[r1*PP + c01];
        al[1][0] = sYl[r0*PP + c10]; al[1][1] = sYl[r0*PP + c11];
        al[1][2] = sYl[r1*PP + c10]; al[1][3] = sYl[r1*PP + c11];
        #pragma unroll
        for (int n = 0; n < 4; n++) {
            int wr = (n*8 + g) * W2P;
            uint32_t bh0 = w2h[wr + r0], bh1 = w2h[wr + r1];
            uint32_t bl0 = w2l[wr + r0], bl1 = w2l[wr + r1];
            #pragma unroll
            for (int m = 0; m < 2; m++) {
                mma_bf16(acc2[n][m], ah[m], bh0, bh1);
                mma_bf16(acc2[n][m], ah[m], bl0, bl1);
                mma_bf16(acc2[n][m], al[m], bh0, bh1);
            }
        }
    }

    // swish + bias -> H2 (pair-rows 0..15)
    #pragma unroll
    for (int n = 0; n < 4; n++) {
        float2 bb = B2v[n*4 + t];
        #pragma unroll
        for (int m = 0; m < 2; m++) {
            int rA = R + m*16 + g, rB = rA + 8;
            float s0 = swishf(acc2[n][m][0] + bb.x);
            float s1 = swishf(acc2[n][m][1] + bb.y);
            float s2 = swishf(acc2[n][m][2] + bb.x);
            float s3 = swishf(acc2[n][m][3] + bb.y);
            uint32_t h01 = pkbf(s1, s0);
            uint32_t l01 = pkbf(s1 - bf_hi(h01), s0 - bf_lo(h01));
            uint32_t h23 = pkbf(s3, s2);
            uint32_t l23 = pkbf(s3 - bf_hi(h23), s2 - bf_lo(h23));
            int ro = (n*4 + t) * PP;
            sYh[ro + rA] = h01; sYl[ro + rA] = l01;
            sYh[ro + rB] = h23; sYl[ro + rB] = l23;
        }
    }
    __syncwarp();

    // ================= layer 3: [128x32] x [32x16] =================
    float acc3[2][2][4];
    #pragma unroll
    for (int n = 0; n < 2; n++)
        #pragma unroll
        for (int m = 0; m < 2; m++)
            #pragma unroll
            for (int r = 0; r < 4; r++) acc3[n][m][r] = 0.f;

    #pragma unroll
    for (int kc = 0; kc < 2; kc++) {
        int r0 = kc * 8 + t, r1 = r0 + 4;
        uint32_t ah[2][4], al[2][4];
        ah[0][0] = sYh[r0*PP + c00]; ah[0][1] = sYh[r0*PP + c01];
        ah[0][2] = sYh[r1*PP + c00]; ah[0][3] = sYh[r1*PP + c01];
        ah[1][0] = sYh[r0*PP + c10]; ah[1][1] = sYh[r0*PP + c11];
        ah[1][2] = sYh[r1*PP + c10]; ah[1][3] = sYh[r1*PP + c11];
        al[0][0] = sYl[r0*PP + c00]; al[0][1] = sYl[r0*PP + c01];
        al[0][2] = sYl[r1*PP + c00]; al[0][3] = sYl[r1*PP + c01];
        al[1][0] = sYl[r0*PP + c10]; al[1][1] = sYl[r0*PP + c11];
        al[1][2] = sYl[r1*PP + c10]; al[1][3] = sYl[r1*PP + c11];
        #pragma unroll
        for (int n = 0; n < 2; n++) {
            int wr = (n*8 + g) * W3P;
            uint32_t bh0 = w3h[wr + r0], bh1 = w3h[wr + r1];
            uint32_t bl0 = w3l[wr + r0], bl1 = w3l[wr + r1];
            #pragma unroll
            for (int m = 0; m < 2; m++) {
                mma_bf16(acc3[n][m], ah[m], bh0, bh1);
                mma_bf16(acc3[n][m], ah[m], bl0, bl1);
                mma_bf16(acc3[n][m], al[m], bh0, bh1);
            }
        }
    }

    // dx (+bias) stored as fp32 rows 0..15, aliasing sYl (all L3 loads already issued)
    float* sDX = (float*)(smem + OFF_YLO);
    #pragma unroll
    for (int n = 0; n < 2; n++) {
        float2 bb = B3v[n*4 + t];
        #pragma unroll
        for (int m = 0; m < 2; m++) {
            int rA = R + m*16 + g, rB = rA + 8;
            int ro = (n*8 + 2*t) * PP;
            sDX[ro + rA]      = acc3[n][m][0] + bb.x;
            sDX[ro + PP + rA] = acc3[n][m][1] + bb.y;
            sDX[ro + rB]      = acc3[n][m][2] + bb.x;
            sDX[ro + PP + rB] = acc3[n][m][3] + bb.y;
        }
    }
    __syncwarp();

    // ---- epilogue: out = x + dx * (noise <= 0.5) ----
    {
        const size_t p = ((size_t)b * S + y) * S + c0 + tid;
        float msk = (noise[p] <= 0.5f) ? 1.f : 0.f;
        float4* out4 = (float4*)out;
        #pragma unroll
        for (int gi = 0; gi < 4; gi++) {
            float4 xv = xin4[p * 4 + gi];
            float4 ov = make_float4(
                xv.x + sDX[(gi*4 + 0)*PP + tid] * msk,
                xv.y + sDX[(gi*4 + 1)*PP + tid] * msk,
                xv.z + sDX[(gi*4 + 2)*PP + tid] * msk,
                xv.w + sDX[(gi*4 + 3)*PP + tid] * msk);
            out4[p * 4 + gi] = ov;
        }
    }
}

extern "C" void kernel_launch(void* const* d_in, const int* in_sizes, int n_in,
                              void* d_out, int out_size) {
    const float* x     = (const float*)d_in[0];
    const float* noise = (const float*)d_in[1];
    const float* W1    = (const float*)d_in[2];
    const float* b1    = (const float*)d_in[3];
    const float* W2    = (const float*)d_in[4];
    const float* b2    = (const float*)d_in[5];
    const float* W3    = (const float*)d_in[6];
    const float* b3    = (const float*)d_in[7];

    cudaFuncSetAttribute(nca_mma, cudaFuncAttributeMaxDynamicSharedMemorySize, SMEM_BYTES);

    prep_weights<<<8, 128>>>(W1, W2, W3);
    nca_mma<<<8192, 128, SMEM_BYTES>>>(x, noise, b1, b2, b3, (float*)d_out);
}

// round 5
// speedup vs baseline: 2.1016x; 1.3792x over previous
#include <cuda_runtime.h>
#include <cstdint>

#define S 512
#define C 16
#define TILE_COLS 130
#define PSTRIDE 20
#define PP 136                 // K-pair-row stride (u32) for transposed activations
#define SDXP 20                // pixel stride (floats) for dx staging

// ---- smem byte offsets ----
#define OFF_YHI   0
#define OFF_YLO   (40*PP*4)                       // 21760
#define OFF_ALIAS (2*40*PP*4)                     // 43520: tile, later W1+biases
#define OFF_TILE  OFF_ALIAS
#define W1P 44
#define OFF_W1H OFF_ALIAS
#define OFF_W1L (OFF_W1H + 64*W1P*4)              // +11264
#define OFF_B1  (OFF_W1L + 64*W1P*4)              // +11264 -> alias+22528
#define OFF_B2  (OFF_B1 + 64*4)
#define OFF_B3  (OFF_B2 + 32*4)
#define SMEM_BYTES (OFF_ALIAS + 31232)            // 74752 (tile needs 31200)

__device__ uint32_t gW1h[64*W1P], gW1l[64*W1P];
__device__ uint4 gW2f[4*4*32];    // [kc][n][lane] -> {bh0,bh1,bl0,bl1}
__device__ uint4 gW3f[2*2*32];

// ---------------- helpers ----------------
static __device__ __forceinline__ uint32_t pkbf(float hi, float lo) {
    uint32_t d; asm("cvt.rn.bf16x2.f32 %0, %1, %2;" : "=r"(d) : "f"(hi), "f"(lo)); return d;
}
static __device__ __forceinline__ float bf_lo(uint32_t v) { return __uint_as_float(v << 16); }
static __device__ __forceinline__ float bf_hi(uint32_t v) { return __uint_as_float(v & 0xffff0000u); }
static __device__ __forceinline__ float swishf(float z) {
    return __fdividef(z, 1.0f + __expf(-z));
}
static __device__ __forceinline__ float getc(float4 v, int i) {
    switch (i & 3) { case 0: return v.x; case 1: return v.y; case 2: return v.z; default: return v.w; }
}
static __device__ __forceinline__ void mma_bf16(float* c, const uint32_t* a,
                                                uint32_t b0, uint32_t b1) {
    asm("mma.sync.aligned.m16n8k16.row.col.f32.bf16.bf16.f32 "
        "{%0,%1,%2,%3}, {%4,%5,%6,%7}, {%8,%9}, {%0,%1,%2,%3};"
        : "+f"(c[0]), "+f"(c[1]), "+f"(c[2]), "+f"(c[3])
        : "r"(a[0]), "r"(a[1]), "r"(a[2]), "r"(a[3]), "r"(b0), "r"(b1));
}

// ---------------- weight prep ----------------
__global__ void prep_weights(const float* __restrict__ W1, const float* __restrict__ W2,
                             const float* __restrict__ W3) {
    int i0 = blockIdx.x * blockDim.x + threadIdx.x;
    int nt = gridDim.x * blockDim.x;
    // W1: transposed hi/lo, padded K-pairs (smem-destined, stride W1P)
    for (int i = i0; i < 64 * W1P; i += nt) {
        int n = i / W1P, jp = i % W1P;
        int k0 = 2 * jp, k1 = k0 + 1;
        float w0 = (k0 < 80) ? W1[k0 * 64 + n] : 0.f;
        float w1v = (k1 < 80) ? W1[k1 * 64 + n] : 0.f;
        uint32_t h = pkbf(w1v, w0);
        gW1h[i] = h;
        gW1l[i] = pkbf(w1v - bf_hi(h), w0 - bf_lo(h));
    }
    // W2/W3: packed per-fragment uint4 {bh0,bh1,bl0,bl1}
    for (int i = i0; i < 4 * 4 * 32; i += nt) {
        int lane = i & 31, n = (i >> 5) & 3, kc = i >> 7;
        int g = lane >> 2, t = lane & 3;
        int col = n * 8 + g;
        int r0 = kc * 8 + t, r1 = r0 + 4;
        float a0 = W2[(2*r0)*32 + col],   a1 = W2[(2*r0+1)*32 + col];
        float c0v = W2[(2*r1)*32 + col],  c1v = W2[(2*r1+1)*32 + col];
        uint32_t h0 = pkbf(a1, a0), h1 = pkbf(c1v, c0v);
        gW2f[i] = make_uint4(h0, h1,
                             pkbf(a1 - bf_hi(h0), a0 - bf_lo(h0)),
                             pkbf(c1v - bf_hi(h1), c0v - bf_lo(h1)));
    }
    for (int i = i0; i < 2 * 2 * 32; i += nt) {
        int lane = i & 31, n = (i >> 5) & 1, kc = i >> 6;
        int g = lane >> 2, t = lane & 3;
        int col = n * 8 + g;
        int r0 = kc * 8 + t, r1 = r0 + 4;
        float a0 = W3[(2*r0)*16 + col],   a1 = W3[(2*r0+1)*16 + col];
        float c0v = W3[(2*r1)*16 + col],  c1v = W3[(2*r1+1)*16 + col];
        uint32_t h0 = pkbf(a1, a0), h1 = pkbf(c1v, c0v);
        gW3f[i] = make_uint4(h0, h1,
                             pkbf(a1 - bf_hi(h0), a0 - bf_lo(h0)),
                             pkbf(c1v - bf_hi(h1), c0v - bf_lo(h1)));
    }
}

// ---------------- main kernel ----------------
__global__ void __launch_bounds__(128, 3) nca_mma(
    const float* __restrict__ xin, const float* __restrict__ noise,
    const float* __restrict__ b1, const float* __restrict__ b2, const float* __restrict__ b3,
    float* __restrict__ out)
{
    extern __shared__ __align__(16) char smem[];
    float* tile = (float*)(smem + OFF_TILE);
    uint32_t* sYh = (uint32_t*)(smem + OFF_YHI);
    uint32_t* sYl = (uint32_t*)(smem + OFF_YLO);

    const int tid = threadIdx.x;
    const int lane = tid & 31;
    const int R = (tid >> 5) * 32;
    const int g = lane >> 2;
    const int t = lane & 3;

    const int blk = blockIdx.x;
    const int c0 = (blk & 3) * 128;
    const int y  = (blk >> 2) & (S - 1);
    const int b  = blk >> 11;

    // ---- tile load: rows y-1..y+1, cols c0-1..c0+128, zero halo ----
    const float4* xin4 = (const float4*)xin;
    #pragma unroll
    for (int it = 0; it < 13; it++) {
        int i = tid + it * 128;
        if (i < 3 * 520) {
            int r = i / 520, rem = i - r * 520;
            int pc = rem >> 2, ch4 = rem & 3;
            int gy = y - 1 + r, gx = c0 - 1 + pc;
            float4 v = make_float4(0.f, 0.f, 0.f, 0.f);
            if ((unsigned)gy < S && (unsigned)gx < S)
                v = xin4[(((size_t)b * S + gy) * S + gx) * 4 + ch4];
            *(float4*)(tile + (r * TILE_COLS + pc) * PSTRIDE + ch4 * 4) = v;
        }
    }
    __syncthreads();

    // ---- perceive -> transposed hi/lo bf16 pairs in smem ----
    const int tc = tid + 1;
    #pragma unroll
    for (int cg = 0; cg < 4; cg++) {
        float4 tt[3][3];
        #pragma unroll
        for (int r = 0; r < 3; r++)
            #pragma unroll
            for (int c = 0; c < 3; c++)
                tt[r][c] = *(const float4*)(tile + (r * TILE_COLS + tc - 1 + c) * PSTRIDE + cg * 4);
        float f[20];
        #pragma unroll
        for (int cc = 0; cc < 4; cc++) {
            float a[3][3];
            #pragma unroll
            for (int r = 0; r < 3; r++)
                #pragma unroll
                for (int c = 0; c < 3; c++)
                    a[r][c] = getc(tt[r][c], cc);
            float e  = a[0][1] + a[1][0] + a[1][2] + a[2][1];
            float co = a[0][0] + a[0][2] + a[2][0] + a[2][2];
            int bs = cc * 5;
            f[bs + 0] = a[1][1];
            f[bs + 1] = ((a[0][2]-a[0][0]) + 2.f*(a[1][2]-a[1][0]) + (a[2][2]-a[2][0])) * 0.125f;
            f[bs + 2] = ((a[2][0]-a[0][0]) + 2.f*(a[2][1]-a[0][1]) + (a[2][2]-a[0][2])) * 0.125f;
            f[bs + 3] = 0.25f*co + 0.5f*e - 3.f*a[1][1];
            f[bs + 4] = (co + e + a[1][1]) * (1.f/9.f);
        }
        #pragma unroll
        for (int i = 0; i < 10; i++) {
            uint32_t h = pkbf(f[2*i+1], f[2*i]);
            uint32_t l = pkbf(f[2*i+1] - bf_hi(h), f[2*i] - bf_lo(h));
            int ro = (cg * 10 + i) * PP + tid;
            sYh[ro] = h;
            sYl[ro] = l;
        }
    }
    __syncthreads();   // Y complete; tile dead -> stage W1 + biases into alias region

    {
        const uint4* sh = (const uint4*)gW1h; uint4* dh = (uint4*)(smem + OFF_W1H);
        for (int i = tid; i < 704; i += 128) dh[i] = sh[i];
        const uint4* sl = (const uint4*)gW1l; uint4* dl = (uint4*)(smem + OFF_W1L);
        for (int i = tid; i < 704; i += 128) dl[i] = sl[i];
        float* B1 = (float*)(smem + OFF_B1);
        float* B2 = (float*)(smem + OFF_B2);
        float* B3 = (float*)(smem + OFF_B3);
        if (tid < 64) B1[tid] = b1[tid];
        else if (tid < 96) B2[tid-64] = b2[tid-64];
        else if (tid < 112) B3[tid-96] = b3[tid-96];
    }
    __syncthreads();

    const uint32_t* w1h = (const uint32_t*)(smem + OFF_W1H);
    const uint32_t* w1l = (const uint32_t*)(smem + OFF_W1L);
    const float2* B1v = (const float2*)(smem + OFF_B1);
    const float2* B2v = (const float2*)(smem + OFF_B2);
    const float2* B3v = (const float2*)(smem + OFF_B3);

    const int c00 = R + g, c01 = R + g + 8, c10 = R + 16 + g, c11 = R + 24 + g;

    // ================= layer 1: [128x80] x [80x64] (W1 from smem) =================
    float acc1[8][2][4];
    #pragma unroll
    for (int n = 0; n < 8; n++)
        #pragma unroll
        for (int m = 0; m < 2; m++)
            #pragma unroll
            for (int r = 0; r < 4; r++) acc1[n][m][r] = 0.f;

    #pragma unroll
    for (int kc = 0; kc < 5; kc++) {
        int r0 = kc * 8 + t, r1 = r0 + 4;
        uint32_t ah[2][4], al[2][4];
        ah[0][0] = sYh[r0*PP + c00]; ah[0][1] = sYh[r0*PP + c01];
        ah[0][2] = sYh[r1*PP + c00]; ah[0][3] = sYh[r1*PP + c01];
        ah[1][0] = sYh[r0*PP + c10]; ah[1][1] = sYh[r0*PP + c11];
        ah[1][2] = sYh[r1*PP + c10]; ah[1][3] = sYh[r1*PP + c11];
        al[0][0] = sYl[r0*PP + c00]; al[0][1] = sYl[r0*PP + c01];
        al[0][2] = sYl[r1*PP + c00]; al[0][3] = sYl[r1*PP + c01];
        al[1][0] = sYl[r0*PP + c10]; al[1][1] = sYl[r0*PP + c11];
        al[1][2] = sYl[r1*PP + c10]; al[1][3] = sYl[r1*PP + c11];
        #pragma unroll
        for (int n = 0; n < 8; n++) {
            int wr = (n*8 + g) * W1P;
            uint32_t bh0 = w1h[wr + r0], bh1 = w1h[wr + r1];
            uint32_t bl0 = w1l[wr + r0], bl1 = w1l[wr + r1];
            #pragma unroll
            for (int m = 0; m < 2; m++) {
                mma_bf16(acc1[n][m], ah[m], bh0, bh1);
                mma_bf16(acc1[n][m], ah[m], bl0, bl1);
                mma_bf16(acc1[n][m], al[m], bh0, bh1);
            }
        }
    }

    // swish + bias -> H1 (pair-rows 0..31)
    #pragma unroll
    for (int n = 0; n < 8; n++) {
        float2 bb = B1v[n*4 + t];
        #pragma unroll
        for (int m = 0; m < 2; m++) {
            int rA = R + m*16 + g, rB = rA + 8;
            float s0 = swishf(acc1[n][m][0] + bb.x);
            float s1 = swishf(acc1[n][m][1] + bb.y);
            float s2 = swishf(acc1[n][m][2] + bb.x);
            float s3 = swishf(acc1[n][m][3] + bb.y);
            uint32_t h01 = pkbf(s1, s0);
            uint32_t l01 = pkbf(s1 - bf_hi(h01), s0 - bf_lo(h01));
            uint32_t h23 = pkbf(s3, s2);
            uint32_t l23 = pkbf(s3 - bf_hi(h23), s2 - bf_lo(h23));
            int ro = (n*4 + t) * PP;
            sYh[ro + rA] = h01; sYl[ro + rA] = l01;
            sYh[ro + rB] = h23; sYl[ro + rB] = l23;
        }
    }
    __syncwarp();

    // ================= layer 2: [128x64] x [64x32] (W2 fragments via LDG) =================
    uint4 w2f[16];
    #pragma unroll
    for (int i = 0; i < 16; i++) w2f[i] = __ldg(&gW2f[i * 32 + lane]);

    float acc2[4][2][4];
    #pragma unroll
    for (int n = 0; n < 4; n++)
        #pragma unroll
        for (int m = 0; m < 2; m++)
            #pragma unroll
            for (int r = 0; r < 4; r++) acc2[n][m][r] = 0.f;

    #pragma unroll
    for (int kc = 0; kc < 4; kc++) {
        int r0 = kc * 8 + t, r1 = r0 + 4;
        uint32_t ah[2][4], al[2][4];
        ah[0][0] = sYh[r0*PP + c00]; ah[0][1] = sYh[r0*PP + c01];
        ah[0][2] = sYh[r1*PP + c00]; ah[0][3] = sYh[r1*PP + c01];
        ah[1][0] = sYh[r0*PP + c10]; ah[1][1] = sYh[r0*PP + c11];
        ah[1][2] = sYh[r1*PP + c10]; ah[1][3] = sYh[r1*PP + c11];
        al[0][0] = sYl[r0*PP + c00]; al[0][1] = sYl[r0*PP + c01];
        al[0][2] = sYl[r1*PP + c00]; al[0][3] = sYl[r1*PP + c01];
        al[1][0] = sYl[r0*PP + c10]; al[1][1] = sYl[r0*PP + c11];
        al[1][2] = sYl[r1*PP + c10]; al[1][3] = sYl[r1*PP + c11];
        #pragma unroll
        for (int n = 0; n < 4; n++) {
            uint4 wf = w2f[kc*4 + n];
            #pragma unroll
            for (int m = 0; m < 2; m++) {
                mma_bf16(acc2[n][m], ah[m], wf.x, wf.y);
                mma_bf16(acc2[n][m], ah[m], wf.z, wf.w);
                mma_bf16(acc2[n][m], al[m], wf.x, wf.y);
            }
        }
    }

    // swish + bias -> H2 (pair-rows 0..15)
    uint4 w3f[4];
    #pragma unroll
    for (int i = 0; i < 4; i++) w3f[i] = __ldg(&gW3f[i * 32 + lane]);

    #pragma unroll
    for (int n = 0; n < 4; n++) {
        float2 bb = B2v[n*4 + t];
        #pragma unroll
        for (int m = 0; m < 2; m++) {
            int rA = R + m*16 + g, rB = rA + 8;
            float s0 = swishf(acc2[n][m][0] + bb.x);
            float s1 = swishf(acc2[n][m][1] + bb.y);
            float s2 = swishf(acc2[n][m][2] + bb.x);
            float s3 = swishf(acc2[n][m][3] + bb.y);
            uint32_t h01 = pkbf(s1, s0);
            uint32_t l01 = pkbf(s1 - bf_hi(h01), s0 - bf_lo(h01));
            uint32_t h23 = pkbf(s3, s2);
            uint32_t l23 = pkbf(s3 - bf_hi(h23), s2 - bf_lo(h23));
            int ro = (n*4 + t) * PP;
            sYh[ro + rA] = h01; sYl[ro + rA] = l01;
            sYh[ro + rB] = h23; sYl[ro + rB] = l23;
        }
    }
    __syncwarp();

    // ================= layer 3: [128x32] x [32x16] =================
    float acc3[2][2][4];
    #pragma unroll
    for (int n = 0; n < 2; n++)
        #pragma unroll
        for (int m = 0; m < 2; m++)
            #pragma unroll
            for (int r = 0; r < 4; r++) acc3[n][m][r] = 0.f;

    #pragma unroll
    for (int kc = 0; kc < 2; kc++) {
        int r0 = kc * 8 + t, r1 = r0 + 4;
        uint32_t ah[2][4], al[2][4];
        ah[0][0] = sYh[r0*PP + c00]; ah[0][1] = sYh[r0*PP + c01];
        ah[0][2] = sYh[r1*PP + c00]; ah[0][3] = sYh[r1*PP + c01];
        ah[1][0] = sYh[r0*PP + c10]; ah[1][1] = sYh[r0*PP + c11];
        ah[1][2] = sYh[r1*PP + c10]; ah[1][3] = sYh[r1*PP + c11];
        al[0][0] = sYl[r0*PP + c00]; al[0][1] = sYl[r0*PP + c01];
        al[0][2] = sYl[r1*PP + c00]; al[0][3] = sYl[r1*PP + c01];
        al[1][0] = sYl[r0*PP + c10]; al[1][1] = sYl[r0*PP + c11];
        al[1][2] = sYl[r1*PP + c10]; al[1][3] = sYl[r1*PP + c11];
        #pragma unroll
        for (int n = 0; n < 2; n++) {
            uint4 wf = w3f[kc*2 + n];
            #pragma unroll
            for (int m = 0; m < 2; m++) {
                mma_bf16(acc3[n][m], ah[m], wf.x, wf.y);
                mma_bf16(acc3[n][m], ah[m], wf.z, wf.w);
                mma_bf16(acc3[n][m], al[m], wf.x, wf.y);
            }
        }
    }

    // ---- dx (+bias) staged pixel-major (aliases Y region after CTA-wide drain) ----
    __syncthreads();
    float* sDX = (float*)smem;
    #pragma unroll
    for (int n = 0; n < 2; n++) {
        float2 bb = B3v[n*4 + t];
        int ch = n*8 + 2*t;
        #pragma unroll
        for (int m = 0; m < 2; m++) {
            int rA = R + m*16 + g, rB = rA + 8;
            *(float2*)&sDX[rA*SDXP + ch] = make_float2(acc3[n][m][0] + bb.x, acc3[n][m][1] + bb.y);
            *(float2*)&sDX[rB*SDXP + ch] = make_float2(acc3[n][m][2] + bb.x, acc3[n][m][3] + bb.y);
        }
    }
    __syncthreads();

    // ---- coalesced epilogue: out = x + dx * (noise <= 0.5) ----
    {
        const size_t pbase = ((size_t)b * S + y) * S + c0;
        float4* out4 = (float4*)out;
        #pragma unroll
        for (int it2 = 0; it2 < 4; it2++) {
            int i = tid + it2 * 128;
            int px = i >> 2, q = i & 3;
            float4 xv = xin4[(pbase + px) * 4 + q];
            float4 dv = *(const float4*)&sDX[px * SDXP + q * 4];
            float msk = (noise[pbase + px] <= 0.5f) ? 1.f : 0.f;
            out4[(pbase + px) * 4 + q] = make_float4(
                xv.x + dv.x * msk, xv.y + dv.y * msk,
                xv.z + dv.z * msk, xv.w + dv.w * msk);
        }
    }
}

extern "C" void kernel_launch(void* const* d_in, const int* in_sizes, int n_in,
                              void* d_out, int out_size) {
    const float* x     = (const float*)d_in[0];
    const float* noise = (const float*)d_in[1];
    const float* W1    = (const float*)d_in[2];
    const float* b1    = (const float*)d_in[3];
    const float* W2    = (const float*)d_in[4];
    const float* b2    = (const float*)d_in[5];
    const float* W3    = (const float*)d_in[6];
    const float* b3    = (const float*)d_in[7];

    cudaFuncSetAttribute(nca_mma, cudaFuncAttributeMaxDynamicSharedMemorySize, SMEM_BYTES);

    prep_weights<<<8, 128>>>(W1, W2, W3);
    nca_mma<<<8192, 128, SMEM_BYTES>>>(x, noise, b1, b2, b3, (float*)d_out);
}

// round 6
// speedup vs baseline: 2.4993x; 1.1892x over previous
#include <cuda_runtime.h>
#include <cstdint>

#define S 512
#define C 16
#define TILE_COLS 130
#define PSTRIDE 20
#define PP 136                 // K-pair-row stride (u32) for transposed Y
#define SDXP 20                // pixel stride (floats) for dx staging

// ---- smem byte offsets ----
#define OFF_YHI   0
#define OFF_YLO   (40*PP*4)                       // 21760
#define OFF_TILE  (2*40*PP*4)                     // 43520
#define OFF_B1    (OFF_TILE + 31232)              // 74752
#define OFF_B2    (OFF_B1 + 64*4)
#define OFF_B3    (OFF_B2 + 32*4)
#define SMEM_BYTES (OFF_B3 + 16*4)                // 75200

__device__ uint4 gW1f[5*8*32];    // [kc][n][lane] -> {bh0,bh1,bl0,bl1}
__device__ uint4 gW2f[4*4*32];
__device__ uint4 gW3f[2*2*32];

// ---------------- helpers ----------------
static __device__ __forceinline__ uint32_t pkbf(float hi, float lo) {
    uint32_t d; asm("cvt.rn.bf16x2.f32 %0, %1, %2;" : "=r"(d) : "f"(hi), "f"(lo)); return d;
}
static __device__ __forceinline__ float bf_lo(uint32_t v) { return __uint_as_float(v << 16); }
static __device__ __forceinline__ float bf_hi(uint32_t v) { return __uint_as_float(v & 0xffff0000u); }
static __device__ __forceinline__ float swishf(float z) {
    return __fdividef(z, 1.0f + __expf(-z));
}
static __device__ __forceinline__ float getc(float4 v, int i) {
    switch (i & 3) { case 0: return v.x; case 1: return v.y; case 2: return v.z; default: return v.w; }
}
static __device__ __forceinline__ void mma_bf16(float* c, const uint32_t* a,
                                                uint32_t b0, uint32_t b1) {
    asm("mma.sync.aligned.m16n8k16.row.col.f32.bf16.bf16.f32 "
        "{%0,%1,%2,%3}, {%4,%5,%6,%7}, {%8,%9}, {%0,%1,%2,%3};"
        : "+f"(c[0]), "+f"(c[1]), "+f"(c[2]), "+f"(c[3])
        : "r"(a[0]), "r"(a[1]), "r"(a[2]), "r"(a[3]), "r"(b0), "r"(b1));
}
// swish + bias on a C-fragment, repack as next-layer A hi/lo bf16x2 pairs
static __device__ __forceinline__ void swish_pack(const float* acc, float2 bb,
                                                  uint32_t* h, uint32_t* l) {
    float s0 = swishf(acc[0] + bb.x);
    float s1 = swishf(acc[1] + bb.y);
    float s2 = swishf(acc[2] + bb.x);
    float s3 = swishf(acc[3] + bb.y);
    h[0] = pkbf(s1, s0); l[0] = pkbf(s1 - bf_hi(h[0]), s0 - bf_lo(h[0]));
    h[1] = pkbf(s3, s2); l[1] = pkbf(s3 - bf_hi(h[1]), s2 - bf_lo(h[1]));
}

// ---------------- weight prep: per-fragment uint4 {bh0,bh1,bl0,bl1} ----------------
static __device__ __forceinline__ uint4 mkfrag(const float* W, int ncols, int col,
                                               int r0, int r1) {
    float a0 = W[(2*r0)*ncols + col],  a1 = W[(2*r0+1)*ncols + col];
    float c0 = W[(2*r1)*ncols + col],  c1 = W[(2*r1+1)*ncols + col];
    uint32_t h0 = pkbf(a1, a0), h1 = pkbf(c1, c0);
    return make_uint4(h0, h1,
                      pkbf(a1 - bf_hi(h0), a0 - bf_lo(h0)),
                      pkbf(c1 - bf_hi(h1), c0 - bf_lo(h1)));
}
__global__ void prep_weights(const float* __restrict__ W1, const float* __restrict__ W2,
                             const float* __restrict__ W3) {
    int i0 = blockIdx.x * blockDim.x + threadIdx.x;
    int nt = gridDim.x * blockDim.x;
    for (int i = i0; i < 5*8*32; i += nt) {
        int lane = i & 31, n = (i >> 5) & 7, kc = i >> 8;
        int g = lane >> 2, t = lane & 3;
        gW1f[i] = mkfrag(W1, 64, n*8 + g, kc*8 + t, kc*8 + t + 4);
    }
    for (int i = i0; i < 4*4*32; i += nt) {
        int lane = i & 31, n = (i >> 5) & 3, kc = i >> 7;
        int g = lane >> 2, t = lane & 3;
        gW2f[i] = mkfrag(W2, 32, n*8 + g, kc*8 + t, kc*8 + t + 4);
    }
    for (int i = i0; i < 2*2*32; i += nt) {
        int lane = i & 31, n = (i >> 5) & 1, kc = i >> 6;
        int g = lane >> 2, t = lane & 3;
        gW3f[i] = mkfrag(W3, 16, n*8 + g, kc*8 + t, kc*8 + t + 4);
    }
}

// ---------------- main kernel ----------------
__global__ void __launch_bounds__(128, 3) nca_mma(
    const float* __restrict__ xin, const float* __restrict__ noise,
    const float* __restrict__ b1, const float* __restrict__ b2, const float* __restrict__ b3,
    float* __restrict__ out)
{
    extern __shared__ __align__(16) char smem[];
    float* tile = (float*)(smem + OFF_TILE);
    uint32_t* sYh = (uint32_t*)(smem + OFF_YHI);
    uint32_t* sYl = (uint32_t*)(smem + OFF_YLO);

    const int tid = threadIdx.x;
    const int lane = tid & 31;
    const int R = (tid >> 5) * 32;
    const int g = lane >> 2;
    const int t = lane & 3;

    const int blk = blockIdx.x;
    const int c0 = (blk & 3) * 128;
    const int y  = (blk >> 2) & (S - 1);
    const int b  = blk >> 11;

    // ---- tile load: rows y-1..y+1, cols c0-1..c0+128, zero halo ----
    const float4* xin4 = (const float4*)xin;
    #pragma unroll
    for (int it = 0; it < 13; it++) {
        int i = tid + it * 128;
        if (i < 3 * 520) {
            int r = i / 520, rem = i - r * 520;
            int pc = rem >> 2, ch4 = rem & 3;
            int gy = y - 1 + r, gx = c0 - 1 + pc;
            float4 v = make_float4(0.f, 0.f, 0.f, 0.f);
            if ((unsigned)gy < S && (unsigned)gx < S)
                v = xin4[(((size_t)b * S + gy) * S + gx) * 4 + ch4];
            *(float4*)(tile + (r * TILE_COLS + pc) * PSTRIDE + ch4 * 4) = v;
        }
    }
    {
        float* B1 = (float*)(smem + OFF_B1);
        float* B2 = (float*)(smem + OFF_B2);
        float* B3 = (float*)(smem + OFF_B3);
        if (tid < 64) B1[tid] = b1[tid];
        else if (tid < 96) B2[tid-64] = b2[tid-64];
        else if (tid < 112) B3[tid-96] = b3[tid-96];
    }
    __syncthreads();

    // ---- perceive -> transposed hi/lo bf16 pairs in smem (warp-local region use) ----
    const int tc = tid + 1;
    #pragma unroll
    for (int cg = 0; cg < 4; cg++) {
        float4 tt[3][3];
        #pragma unroll
        for (int r = 0; r < 3; r++)
            #pragma unroll
            for (int c = 0; c < 3; c++)
                tt[r][c] = *(const float4*)(tile + (r * TILE_COLS + tc - 1 + c) * PSTRIDE + cg * 4);
        float f[20];
        #pragma unroll
        for (int cc = 0; cc < 4; cc++) {
            float a[3][3];
            #pragma unroll
            for (int r = 0; r < 3; r++)
                #pragma unroll
                for (int c = 0; c < 3; c++)
                    a[r][c] = getc(tt[r][c], cc);
            float e  = a[0][1] + a[1][0] + a[1][2] + a[2][1];
            float co = a[0][0] + a[0][2] + a[2][0] + a[2][2];
            int bs = cc * 5;
            f[bs + 0] = a[1][1];
            f[bs + 1] = ((a[0][2]-a[0][0]) + 2.f*(a[1][2]-a[1][0]) + (a[2][2]-a[2][0])) * 0.125f;
            f[bs + 2] = ((a[2][0]-a[0][0]) + 2.f*(a[2][1]-a[0][1]) + (a[2][2]-a[0][2])) * 0.125f;
            f[bs + 3] = 0.25f*co + 0.5f*e - 3.f*a[1][1];
            f[bs + 4] = (co + e + a[1][1]) * (1.f/9.f);
        }
        #pragma unroll
        for (int i = 0; i < 10; i++) {
            uint32_t h = pkbf(f[2*i+1], f[2*i]);
            uint32_t l = pkbf(f[2*i+1] - bf_hi(h), f[2*i] - bf_lo(h));
            int ro = (cg * 10 + i) * PP + tid;
            sYh[ro] = h;
            sYl[ro] = l;
        }
    }
    __syncwarp();   // Y region is warp-local (cols R..R+31 written & read by this warp)

    const float2* B1v = (const float2*)(smem + OFF_B1);
    const float2* B2v = (const float2*)(smem + OFF_B2);
    const float2* B3v = (const float2*)(smem + OFF_B3);

    const int c00 = R + g, c01 = R + g + 8, c10 = R + 16 + g, c11 = R + 24 + g;

    // ================= layer 1: [128x80] x [80x64], W1 frags via LDG =================
    float acc1[8][2][4];
    #pragma unroll
    for (int n = 0; n < 8; n++)
        #pragma unroll
        for (int m = 0; m < 2; m++)
            #pragma unroll
            for (int r = 0; r < 4; r++) acc1[n][m][r] = 0.f;

    #pragma unroll
    for (int kc = 0; kc < 5; kc++) {
        uint4 wf[8];
        #pragma unroll
        for (int n = 0; n < 8; n++) wf[n] = __ldg(&gW1f[(kc*8 + n)*32 + lane]);

        int r0 = kc * 8 + t, r1 = r0 + 4;
        uint32_t ah[2][4], al[2][4];
        ah[0][0] = sYh[r0*PP + c00]; ah[0][1] = sYh[r0*PP + c01];
        ah[0][2] = sYh[r1*PP + c00]; ah[0][3] = sYh[r1*PP + c01];
        ah[1][0] = sYh[r0*PP + c10]; ah[1][1] = sYh[r0*PP + c11];
        ah[1][2] = sYh[r1*PP + c10]; ah[1][3] = sYh[r1*PP + c11];
        al[0][0] = sYl[r0*PP + c00]; al[0][1] = sYl[r0*PP + c01];
        al[0][2] = sYl[r1*PP + c00]; al[0][3] = sYl[r1*PP + c01];
        al[1][0] = sYl[r0*PP + c10]; al[1][1] = sYl[r0*PP + c11];
        al[1][2] = sYl[r1*PP + c10]; al[1][3] = sYl[r1*PP + c11];
        #pragma unroll
        for (int n = 0; n < 8; n++) {
            #pragma unroll
            for (int m = 0; m < 2; m++) {
                mma_bf16(acc1[n][m], ah[m], wf[n].x, wf[n].y);
                mma_bf16(acc1[n][m], ah[m], wf[n].z, wf[n].w);
                mma_bf16(acc1[n][m], al[m], wf[n].x, wf[n].y);
            }
        }
    }

    // ---- H1 = swish(acc1 + b1): register-local repack to next-layer A fragments ----
    uint32_t h1h[8][2][2], h1l[8][2][2];
    #pragma unroll
    for (int n = 0; n < 8; n++) {
        float2 bb = B1v[n*4 + t];
        #pragma unroll
        for (int m = 0; m < 2; m++)
            swish_pack(acc1[n][m], bb, h1h[n][m], h1l[n][m]);
    }

    // ================= layer 2: [128x64] x [64x32], A from registers =================
    float acc2[4][2][4];
    #pragma unroll
    for (int n = 0; n < 4; n++)
        #pragma unroll
        for (int m = 0; m < 2; m++)
            #pragma unroll
            for (int r = 0; r < 4; r++) acc2[n][m][r] = 0.f;

    #pragma unroll
    for (int kc = 0; kc < 4; kc++) {
        uint4 wf[4];
        #pragma unroll
        for (int n = 0; n < 4; n++) wf[n] = __ldg(&gW2f[(kc*4 + n)*32 + lane]);
        #pragma unroll
        for (int m = 0; m < 2; m++) {
            uint32_t ah[4] = { h1h[2*kc][m][0], h1h[2*kc][m][1],
                               h1h[2*kc+1][m][0], h1h[2*kc+1][m][1] };
            uint32_t al[4] = { h1l[2*kc][m][0], h1l[2*kc][m][1],
                               h1l[2*kc+1][m][0], h1l[2*kc+1][m][1] };
            #pragma unroll
            for (int n = 0; n < 4; n++) {
                mma_bf16(acc2[n][m], ah, wf[n].x, wf[n].y);
                mma_bf16(acc2[n][m], ah, wf[n].z, wf[n].w);
                mma_bf16(acc2[n][m], al, wf[n].x, wf[n].y);
            }
        }
    }

    // ---- H2 = swish(acc2 + b2): register-local repack ----
    uint32_t h2h[4][2][2], h2l[4][2][2];
    #pragma unroll
    for (int n = 0; n < 4; n++) {
        float2 bb = B2v[n*4 + t];
        #pragma unroll
        for (int m = 0; m < 2; m++)
            swish_pack(acc2[n][m], bb, h2h[n][m], h2l[n][m]);
    }

    // ================= layer 3: [128x32] x [32x16] =================
    float acc3[2][2][4];
    #pragma unroll
    for (int n = 0; n < 2; n++)
        #pragma unroll
        for (int m = 0; m < 2; m++)
            #pragma unroll
            for (int r = 0; r < 4; r++) acc3[n][m][r] = 0.f;

    #pragma unroll
    for (int kc = 0; kc < 2; kc++) {
        uint4 wf[2];
        #pragma unroll
        for (int n = 0; n < 2; n++) wf[n] = __ldg(&gW3f[(kc*2 + n)*32 + lane]);
        #pragma unroll
        for (int m = 0; m < 2; m++) {
            uint32_t ah[4] = { h2h[2*kc][m][0], h2h[2*kc][m][1],
                               h2h[2*kc+1][m][0], h2h[2*kc+1][m][1] };
            uint32_t al[4] = { h2l[2*kc][m][0], h2l[2*kc][m][1],
                               h2l[2*kc+1][m][0], h2l[2*kc+1][m][1] };
            #pragma unroll
            for (int n = 0; n < 2; n++) {
                mma_bf16(acc3[n][m], ah, wf[n].x, wf[n].y);
                mma_bf16(acc3[n][m], ah, wf[n].z, wf[n].w);
                mma_bf16(acc3[n][m], al, wf[n].x, wf[n].y);
            }
        }
    }

    // ---- dx (+bias) staged pixel-major into sYh alias (CTA-wide drain first) ----
    __syncthreads();
    float* sDX = (float*)smem;
    #pragma unroll
    for (int n = 0; n < 2; n++) {
        float2 bb = B3v[n*4 + t];
        int ch = n*8 + 2*t;
        #pragma unroll
        for (int m = 0; m < 2; m++) {
            int rA = R + m*16 + g, rB = rA + 8;
            *(float2*)&sDX[rA*SDXP + ch] = make_float2(acc3[n][m][0] + bb.x, acc3[n][m][1] + bb.y);
            *(float2*)&sDX[rB*SDXP + ch] = make_float2(acc3[n][m][2] + bb.x, acc3[n][m][3] + bb.y);
        }
    }
    __syncthreads();

    // ---- coalesced epilogue: out = x + dx * (noise <= 0.5) ----
    {
        const size_t pbase = ((size_t)b * S + y) * S + c0;
        float4* out4 = (float4*)out;
        #pragma unroll
        for (int it2 = 0; it2 < 4; it2++) {
            int i = tid + it2 * 128;
            int px = i >> 2, q = i & 3;
            float4 xv = xin4[(pbase + px) * 4 + q];
            float4 dv = *(const float4*)&sDX[px * SDXP + q * 4];
            float msk = (noise[pbase + px] <= 0.5f) ? 1.f : 0.f;
            out4[(pbase + px) * 4 + q] = make_float4(
                xv.x + dv.x * msk, xv.y + dv.y * msk,
                xv.z + dv.z * msk, xv.w + dv.w * msk);
        }
    }
}

extern "C" void kernel_launch(void* const* d_in, const int* in_sizes, int n_in,
                              void* d_out, int out_size) {
    const float* x     = (const float*)d_in[0];
    const float* noise = (const float*)d_in[1];
    const float* W1    = (const float*)d_in[2];
    const float* b1    = (const float*)d_in[3];
    const float* W2    = (const float*)d_in[4];
    const float* b2    = (const float*)d_in[5];
    const float* W3    = (const float*)d_in[6];
    const float* b3    = (const float*)d_in[7];

    cudaFuncSetAttribute(nca_mma, cudaFuncAttributeMaxDynamicSharedMemorySize, SMEM_BYTES);

    prep_weights<<<10, 128>>>(W1, W2, W3);
    nca_mma<<<8192, 128, SMEM_BYTES>>>(x, noise, b1, b2, b3, (float*)d_out);
}

// round 7
// speedup vs baseline: 2.8031x; 1.1216x over previous
#include <cuda_runtime.h>
#include <cstdint>

#define S 512
#define C 16
#define TILE_COLS 130
#define PP 136                 // K-pair-row stride (u32) for transposed Y
#define SDXP 20                // pixel stride (floats) for dx staging

// ---- smem byte offsets ----
#define OFF_YHI   0
#define OFF_YLO   (40*PP*4)                       // 21760
#define OFF_TILE  (2*40*PP*4)                     // 43520 ; 2-cg tile: 3*130*8 floats = 12480 B
#define OFF_B1    (OFF_TILE + 12480)              // 56000
#define OFF_B2    (OFF_B1 + 64*4)
#define OFF_B3    (OFF_B2 + 32*4)
#define SMEM_BYTES (OFF_B3 + 16*4)                // 56448 -> 4 CTAs/SM

__device__ uint4 gW1f[5*8*32];    // [kc][n][lane] -> {bh0,bh1,bl0,bl1}
__device__ uint4 gW2f[4*4*32];
__device__ uint4 gW3f[2*2*32];

// ---------------- helpers ----------------
static __device__ __forceinline__ uint32_t pkbf(float hi, float lo) {
    uint32_t d; asm("cvt.rn.bf16x2.f32 %0, %1, %2;" : "=r"(d) : "f"(hi), "f"(lo)); return d;
}
static __device__ __forceinline__ float bf_lo(uint32_t v) { return __uint_as_float(v << 16); }
static __device__ __forceinline__ float bf_hi(uint32_t v) { return __uint_as_float(v & 0xffff0000u); }
static __device__ __forceinline__ float swishf(float z) {
    return __fdividef(z, 1.0f + __expf(-z));
}
static __device__ __forceinline__ float getc(float4 v, int i) {
    switch (i & 3) { case 0: return v.x; case 1: return v.y; case 2: return v.z; default: return v.w; }
}
static __device__ __forceinline__ void mma_bf16(float* c, const uint32_t* a,
                                                uint32_t b0, uint32_t b1) {
    asm("mma.sync.aligned.m16n8k16.row.col.f32.bf16.bf16.f32 "
        "{%0,%1,%2,%3}, {%4,%5,%6,%7}, {%8,%9}, {%0,%1,%2,%3};"
        : "+f"(c[0]), "+f"(c[1]), "+f"(c[2]), "+f"(c[3])
        : "r"(a[0]), "r"(a[1]), "r"(a[2]), "r"(a[3]), "r"(b0), "r"(b1));
}
static __device__ __forceinline__ void swish_pack(const float* acc, float2 bb,
                                                  uint32_t* h, uint32_t* l) {
    float s0 = swishf(acc[0] + bb.x);
    float s1 = swishf(acc[1] + bb.y);
    float s2 = swishf(acc[2] + bb.x);
    float s3 = swishf(acc[3] + bb.y);
    h[0] = pkbf(s1, s0); l[0] = pkbf(s1 - bf_hi(h[0]), s0 - bf_lo(h[0]));
    h[1] = pkbf(s3, s2); l[1] = pkbf(s3 - bf_hi(h[1]), s2 - bf_lo(h[1]));
}

// ---------------- weight prep: per-fragment uint4 {bh0,bh1,bl0,bl1} ----------------
static __device__ __forceinline__ uint4 mkfrag(const float* W, int ncols, int col,
                                               int r0, int r1) {
    float a0 = W[(2*r0)*ncols + col],  a1 = W[(2*r0+1)*ncols + col];
    float c0 = W[(2*r1)*ncols + col],  c1 = W[(2*r1+1)*ncols + col];
    uint32_t h0 = pkbf(a1, a0), h1 = pkbf(c1, c0);
    return make_uint4(h0, h1,
                      pkbf(a1 - bf_hi(h0), a0 - bf_lo(h0)),
                      pkbf(c1 - bf_hi(h1), c0 - bf_lo(h1)));
}
__global__ void prep_weights(const float* __restrict__ W1, const float* __restrict__ W2,
                             const float* __restrict__ W3) {
    int i0 = blockIdx.x * blockDim.x + threadIdx.x;
    int nt = gridDim.x * blockDim.x;
    for (int i = i0; i < 5*8*32; i += nt) {
        int lane = i & 31, n = (i >> 5) & 7, kc = i >> 8;
        int g = lane >> 2, t = lane & 3;
        gW1f[i] = mkfrag(W1, 64, n*8 + g, kc*8 + t, kc*8 + t + 4);
    }
    for (int i = i0; i < 4*4*32; i += nt) {
        int lane = i & 31, n = (i >> 5) & 3, kc = i >> 7;
        int g = lane >> 2, t = lane & 3;
        gW2f[i] = mkfrag(W2, 32, n*8 + g, kc*8 + t, kc*8 + t + 4);
    }
    for (int i = i0; i < 2*2*32; i += nt) {
        int lane = i & 31, n = (i >> 5) & 1, kc = i >> 6;
        int g = lane >> 2, t = lane & 3;
        gW3f[i] = mkfrag(W3, 16, n*8 + g, kc*8 + t, kc*8 + t + 4);
    }
}

// ---------------- main kernel ----------------
__global__ void __launch_bounds__(128, 4) nca_mma(
    const float* __restrict__ xin, const float* __restrict__ noise,
    const float* __restrict__ b1, const float* __restrict__ b2, const float* __restrict__ b3,
    float* __restrict__ out)
{
    extern __shared__ __align__(16) char smem[];
    float4* tile4 = (float4*)(smem + OFF_TILE);
    uint32_t* sYh = (uint32_t*)(smem + OFF_YHI);
    uint32_t* sYl = (uint32_t*)(smem + OFF_YLO);

    const int tid = threadIdx.x;
    const int lane = tid & 31;
    const int R = (tid >> 5) * 32;
    const int g = lane >> 2;
    const int t = lane & 3;

    const int blk = blockIdx.x;
    const int c0 = (blk & 3) * 128;
    const int y  = (blk >> 2) & (S - 1);
    const int b  = blk >> 11;

    const float4* xin4 = (const float4*)xin;
    {
        float* B1 = (float*)(smem + OFF_B1);
        float* B2 = (float*)(smem + OFF_B2);
        float* B3 = (float*)(smem + OFF_B3);
        if (tid < 64) B1[tid] = b1[tid];
        else if (tid < 96) B2[tid-64] = b2[tid-64];
        else if (tid < 112) B3[tid-96] = b3[tid-96];
    }

    // ---- perceive in 2 passes of 2 channel-groups; tile is XOR-swizzled ----
    const int tc = tid + 1;
    #pragma unroll 1
    for (int p = 0; p < 2; p++) {
        if (p > 0) __syncthreads();          // prior pass's tile reads complete
        // load 2-cg tile: rows y-1..y+1, cols c0-1..c0+128, zero halo
        #pragma unroll
        for (int it = 0; it < 7; it++) {
            int i = tid + it * 128;
            if (i < 780) {
                int r = i / 260, rem = i - r * 260;
                int pc = rem >> 1, ch = rem & 1;
                int gy = y - 1 + r, gx = c0 - 1 + pc;
                float4 v = make_float4(0.f, 0.f, 0.f, 0.f);
                if ((unsigned)gy < S && (unsigned)gx < S)
                    v = xin4[(((size_t)b * S + gy) * S + gx) * 4 + p * 2 + ch];
                int fi = ((r * TILE_COLS + pc) << 1) + (ch ^ ((pc >> 2) & 1));
                tile4[fi] = v;
            }
        }
        __syncthreads();

        #pragma unroll
        for (int cgl = 0; cgl < 2; cgl++) {
            float4 tt[3][3];
            #pragma unroll
            for (int r = 0; r < 3; r++)
                #pragma unroll
                for (int c = 0; c < 3; c++) {
                    int pc = tc - 1 + c;
                    int fi = ((r * TILE_COLS + pc) << 1) + (cgl ^ ((pc >> 2) & 1));
                    tt[r][c] = tile4[fi];
                }
            float f[20];
            #pragma unroll
            for (int cc = 0; cc < 4; cc++) {
                float a[3][3];
                #pragma unroll
                for (int r = 0; r < 3; r++)
                    #pragma unroll
                    for (int c = 0; c < 3; c++)
                        a[r][c] = getc(tt[r][c], cc);
                float e  = a[0][1] + a[1][0] + a[1][2] + a[2][1];
                float co = a[0][0] + a[0][2] + a[2][0] + a[2][2];
                int bs = cc * 5;
                f[bs + 0] = a[1][1];
                f[bs + 1] = ((a[0][2]-a[0][0]) + 2.f*(a[1][2]-a[1][0]) + (a[2][2]-a[2][0])) * 0.125f;
                f[bs + 2] = ((a[2][0]-a[0][0]) + 2.f*(a[2][1]-a[0][1]) + (a[2][2]-a[0][2])) * 0.125f;
                f[bs + 3] = 0.25f*co + 0.5f*e - 3.f*a[1][1];
                f[bs + 4] = (co + e + a[1][1]) * (1.f/9.f);
            }
            int cg = p * 2 + cgl;
            #pragma unroll
            for (int i = 0; i < 10; i++) {
                uint32_t h = pkbf(f[2*i+1], f[2*i]);
                uint32_t l = pkbf(f[2*i+1] - bf_hi(h), f[2*i] - bf_lo(h));
                int ro = (cg * 10 + i) * PP + tid;
                sYh[ro] = h;
                sYl[ro] = l;
            }
        }
    }
    __syncwarp();   // Y cols R..R+31 are warp-local from here on

    const float2* B1v = (const float2*)(smem + OFF_B1);
    const float2* B2v = (const float2*)(smem + OFF_B2);
    const float2* B3v = (const float2*)(smem + OFF_B3);

    const int c00 = R + g, c01 = R + g + 8, c10 = R + 16 + g, c11 = R + 24 + g;

    // ================= layer 1: [128x80] x [80x64], W1 frags via LDG =================
    float acc1[8][2][4];
    #pragma unroll
    for (int n = 0; n < 8; n++)
        #pragma unroll
        for (int m = 0; m < 2; m++)
            #pragma unroll
            for (int r = 0; r < 4; r++) acc1[n][m][r] = 0.f;

    #pragma unroll
    for (int kc = 0; kc < 5; kc++) {
        uint4 wf[8];
        #pragma unroll
        for (int n = 0; n < 8; n++) wf[n] = __ldg(&gW1f[(kc*8 + n)*32 + lane]);

        int r0 = kc * 8 + t, r1 = r0 + 4;
        uint32_t ah[2][4], al[2][4];
        ah[0][0] = sYh[r0*PP + c00]; ah[0][1] = sYh[r0*PP + c01];
        ah[0][2] = sYh[r1*PP + c00]; ah[0][3] = sYh[r1*PP + c01];
        ah[1][0] = sYh[r0*PP + c10]; ah[1][1] = sYh[r0*PP + c11];
        ah[1][2] = sYh[r1*PP + c10]; ah[1][3] = sYh[r1*PP + c11];
        al[0][0] = sYl[r0*PP + c00]; al[0][1] = sYl[r0*PP + c01];
        al[0][2] = sYl[r1*PP + c00]; al[0][3] = sYl[r1*PP + c01];
        al[1][0] = sYl[r0*PP + c10]; al[1][1] = sYl[r0*PP + c11];
        al[1][2] = sYl[r1*PP + c10]; al[1][3] = sYl[r1*PP + c11];
        #pragma unroll
        for (int n = 0; n < 8; n++) {
            #pragma unroll
            for (int m = 0; m < 2; m++) {
                mma_bf16(acc1[n][m], ah[m], wf[n].x, wf[n].y);
                mma_bf16(acc1[n][m], ah[m], wf[n].z, wf[n].w);
                mma_bf16(acc1[n][m], al[m], wf[n].x, wf[n].y);
            }
        }
    }

    // ---- H1 = swish(acc1 + b1): register-local repack ----
    uint32_t h1h[8][2][2], h1l[8][2][2];
    #pragma unroll
    for (int n = 0; n < 8; n++) {
        float2 bb = B1v[n*4 + t];
        #pragma unroll
        for (int m = 0; m < 2; m++)
            swish_pack(acc1[n][m], bb, h1h[n][m], h1l[n][m]);
    }

    // ================= layer 2: [128x64] x [64x32], A from registers =================
    float acc2[4][2][4];
    #pragma unroll
    for (int n = 0; n < 4; n++)
        #pragma unroll
        for (int m = 0; m < 2; m++)
            #pragma unroll
            for (int r = 0; r < 4; r++) acc2[n][m][r] = 0.f;

    #pragma unroll
    for (int kc = 0; kc < 4; kc++) {
        uint4 wf[4];
        #pragma unroll
        for (int n = 0; n < 4; n++) wf[n] = __ldg(&gW2f[(kc*4 + n)*32 + lane]);
        #pragma unroll
        for (int m = 0; m < 2; m++) {
            uint32_t ah[4] = { h1h[2*kc][m][0], h1h[2*kc][m][1],
                               h1h[2*kc+1][m][0], h1h[2*kc+1][m][1] };
            uint32_t al[4] = { h1l[2*kc][m][0], h1l[2*kc][m][1],
                               h1l[2*kc+1][m][0], h1l[2*kc+1][m][1] };
            #pragma unroll
            for (int n = 0; n < 4; n++) {
                mma_bf16(acc2[n][m], ah, wf[n].x, wf[n].y);
                mma_bf16(acc2[n][m], ah, wf[n].z, wf[n].w);
                mma_bf16(acc2[n][m], al, wf[n].x, wf[n].y);
            }
        }
    }

    // ---- H2 = swish(acc2 + b2) ----
    uint32_t h2h[4][2][2], h2l[4][2][2];
    #pragma unroll
    for (int n = 0; n < 4; n++) {
        float2 bb = B2v[n*4 + t];
        #pragma unroll
        for (int m = 0; m < 2; m++)
            swish_pack(acc2[n][m], bb, h2h[n][m], h2l[n][m]);
    }

    // ================= layer 3: [128x32] x [32x16] =================
    float acc3[2][2][4];
    #pragma unroll
    for (int n = 0; n < 2; n++)
        #pragma unroll
        for (int m = 0; m < 2; m++)
            #pragma unroll
            for (int r = 0; r < 4; r++) acc3[n][m][r] = 0.f;

    #pragma unroll
    for (int kc = 0; kc < 2; kc++) {
        uint4 wf[2];
        #pragma unroll
        for (int n = 0; n < 2; n++) wf[n] = __ldg(&gW3f[(kc*2 + n)*32 + lane]);
        #pragma unroll
        for (int m = 0; m < 2; m++) {
            uint32_t ah[4] = { h2h[2*kc][m][0], h2h[2*kc][m][1],
                               h2h[2*kc+1][m][0], h2h[2*kc+1][m][1] };
            uint32_t al[4] = { h2l[2*kc][m][0], h2l[2*kc][m][1],
                               h2l[2*kc+1][m][0], h2l[2*kc+1][m][1] };
            #pragma unroll
            for (int n = 0; n < 2; n++) {
                mma_bf16(acc3[n][m], ah, wf[n].x, wf[n].y);
                mma_bf16(acc3[n][m], ah, wf[n].z, wf[n].w);
                mma_bf16(acc3[n][m], al, wf[n].x, wf[n].y);
            }
        }
    }

    // ---- dx (+bias) staged pixel-major into Y alias (CTA-wide drain first) ----
    __syncthreads();
    float* sDX = (float*)smem;
    #pragma unroll
    for (int n = 0; n < 2; n++) {
        float2 bb = B3v[n*4 + t];
        int ch = n*8 + 2*t;
        #pragma unroll
        for (int m = 0; m < 2; m++) {
            int rA = R + m*16 + g, rB = rA + 8;
            *(float2*)&sDX[rA*SDXP + ch] = make_float2(acc3[n][m][0] + bb.x, acc3[n][m][1] + bb.y);
            *(float2*)&sDX[rB*SDXP + ch] = make_float2(acc3[n][m][2] + bb.x, acc3[n][m][3] + bb.y);
        }
    }
    __syncthreads();

    // ---- coalesced epilogue: out = x + dx * (noise <= 0.5) ----
    {
        const size_t pbase = ((size_t)b * S + y) * S + c0;
        float4* out4 = (float4*)out;
        #pragma unroll
        for (int it2 = 0; it2 < 4; it2++) {
            int i = tid + it2 * 128;
            int px = i >> 2, q = i & 3;
            float4 xv = xin4[(pbase + px) * 4 + q];
            float4 dv = *(const float4*)&sDX[px * SDXP + q * 4];
            float msk = (noise[pbase + px] <= 0.5f) ? 1.f : 0.f;
            out4[(pbase + px) * 4 + q] = make_float4(
                xv.x + dv.x * msk, xv.y + dv.y * msk,
                xv.z + dv.z * msk, xv.w + dv.w * msk);
        }
    }
}

extern "C" void kernel_launch(void* const* d_in, const int* in_sizes, int n_in,
                              void* d_out, int out_size) {
    const float* x     = (const float*)d_in[0];
    const float* noise = (const float*)d_in[1];
    const float* W1    = (const float*)d_in[2];
    const float* b1    = (const float*)d_in[3];
    const float* W2    = (const float*)d_in[4];
    const float* b2    = (const float*)d_in[5];
    const float* W3    = (const float*)d_in[6];
    const float* b3    = (const float*)d_in[7];

    cudaFuncSetAttribute(nca_mma, cudaFuncAttributeMaxDynamicSharedMemorySize, SMEM_BYTES);

    prep_weights<<<10, 128>>>(W1, W2, W3);
    nca_mma<<<8192, 128, SMEM_BYTES>>>(x, noise, b1, b2, b3, (float*)d_out);
}